// round 3
// baseline (speedup 1.0000x reference)
#include <cuda_runtime.h>

// CombinedLoss: surface(idc=[1]) + tversky(alpha=beta=0.5, smooth=1)
//
// Analytic collapse of the reference: the EDT runs over 4 axes INCLUDING the
// channel axis of a one-hot(argmax) mask with C=3. For channel 1:
//   - every pos voxel has a zero neighbor one channel-step away (argmax is
//     unique), so pos_d == 1  =>  (pos_d - 1)*posf == 0
//   - every neg voxel (argmax in {0,2}) has a pos voxel one channel-step
//     away, so neg_d == 1
// int32 truncation is identity on {0,1}, hence exactly:
//   dist_maps[:,1] = 1{argmax(probs, axis=1) != 1}
//   surface = mean(probs[:,1] * 1{argmax != 1})       over B*D*H*W voxels
//   tversky = 1 - (tp+1)/(tp + 0.5*(sum_p - tp) + 0.5*(sum_t - tp) + 1)
// argmax first-occurrence: argmax==1 iff p1 > p0 && p1 >= p2.
//
// Shapes: probs/target [B=2, C=3, D=64, H=128, W=128] fp32. Output: scalar.
//
// Geometry: 1024 blocks x 256 threads, one float4 group per thread per batch
// (b=0 and b=1 mirrored) => single wave on 148 SMs at occ<=8, 12 independent
// LDG.128 per thread, no integer division.

#define SPATIAL   (64 * 128 * 128)       // 1,048,576 per (b,c)
#define SPATIAL4  (SPATIAL / 4)          // 262,144 float4 groups per (b,c)
#define NVOX      (2 * SPATIAL)          // 2,097,152 voxels
#define NBLK      1024
#define NTHR      256
// NBLK*NTHR = 262,144 threads = SPATIAL4: thread i handles group i of batch 0
// and group i of batch 1.

__device__ float g_part[NBLK * 4];
__device__ unsigned int g_count = 0;     // self-resetting (graph-replay safe)

__global__ __launch_bounds__(NTHR, 8)
void combined_loss_fused(const float* __restrict__ probs,
                         const float* __restrict__ target,
                         float* __restrict__ out)
{
    const int s4   = blockIdx.x * NTHR + threadIdx.x;  // 0 .. 262143
    const int e0   = s4 * 4;                           // batch 0 offset
    const int e1   = 3 * SPATIAL + e0;                 // batch 1 offset

    // 12 independent 128-bit loads, front-batched for MLP.
    const float4 A0 = *(const float4*)(probs  + e0);
    const float4 A1 = *(const float4*)(probs  + e0 + SPATIAL);
    const float4 A2 = *(const float4*)(probs  + e0 + 2 * SPATIAL);
    const float4 B0 = *(const float4*)(probs  + e1);
    const float4 B1 = *(const float4*)(probs  + e1 + SPATIAL);
    const float4 B2 = *(const float4*)(probs  + e1 + 2 * SPATIAL);
    const float4 X0 = *(const float4*)(target + e0);
    const float4 X1 = *(const float4*)(target + e0 + SPATIAL);
    const float4 X2 = *(const float4*)(target + e0 + 2 * SPATIAL);
    const float4 Y0 = *(const float4*)(target + e1);
    const float4 Y1 = *(const float4*)(target + e1 + SPATIAL);
    const float4 Y2 = *(const float4*)(target + e1 + 2 * SPATIAL);

    float snum = 0.f, tp = 0.f, sp = 0.f, st = 0.f;

#define LANE(P0, P1, P2, T0, T1, T2, k) do {                          \
        const float a = P0.k, q = P1.k, c = P2.k;                     \
        const float x = T0.k, y = T1.k, z = T2.k;                     \
        /* argmax != 1  <=>  !(p1 > p0 && p1 >= p2) */                \
        if (a >= q || c > q) snum += q;                               \
        tp += a * x + q * y + c * z;                                  \
        sp += a + q + c;                                              \
        st += x + y + z;                                              \
    } while (0)

    LANE(A0, A1, A2, X0, X1, X2, x);
    LANE(A0, A1, A2, X0, X1, X2, y);
    LANE(A0, A1, A2, X0, X1, X2, z);
    LANE(A0, A1, A2, X0, X1, X2, w);
    LANE(B0, B1, B2, Y0, Y1, Y2, x);
    LANE(B0, B1, B2, Y0, Y1, Y2, y);
    LANE(B0, B1, B2, Y0, Y1, Y2, z);
    LANE(B0, B1, B2, Y0, Y1, Y2, w);
#undef LANE

    // intra-warp tree reduction of the 4 accumulators
    #pragma unroll
    for (int o = 16; o > 0; o >>= 1) {
        snum += __shfl_down_sync(0xffffffffu, snum, o);
        tp   += __shfl_down_sync(0xffffffffu, tp,   o);
        sp   += __shfl_down_sync(0xffffffffu, sp,   o);
        st   += __shfl_down_sync(0xffffffffu, st,   o);
    }

    __shared__ float sm[8][4];
    const int lane = threadIdx.x & 31;
    const int wid  = threadIdx.x >> 5;
    if (lane == 0) {
        sm[wid][0] = snum; sm[wid][1] = tp; sm[wid][2] = sp; sm[wid][3] = st;
    }
    __syncthreads();

    if (threadIdx.x < 32) {
        float v0 = (lane < 8) ? sm[lane][0] : 0.f;
        float v1 = (lane < 8) ? sm[lane][1] : 0.f;
        float v2 = (lane < 8) ? sm[lane][2] : 0.f;
        float v3 = (lane < 8) ? sm[lane][3] : 0.f;
        #pragma unroll
        for (int o = 4; o > 0; o >>= 1) {
            v0 += __shfl_down_sync(0xffffffffu, v0, o);
            v1 += __shfl_down_sync(0xffffffffu, v1, o);
            v2 += __shfl_down_sync(0xffffffffu, v2, o);
            v3 += __shfl_down_sync(0xffffffffu, v3, o);
        }
        if (lane == 0) {
            g_part[blockIdx.x * 4 + 0] = v0;
            g_part[blockIdx.x * 4 + 1] = v1;
            g_part[blockIdx.x * 4 + 2] = v2;
            g_part[blockIdx.x * 4 + 3] = v3;
        }
    }

    // ---- fused last-block finisher (single launch in the graph) ----
    __shared__ unsigned int s_ticket;
    __threadfence();                      // publish g_part before the ticket
    __syncthreads();
    if (threadIdx.x == 0)
        s_ticket = atomicAdd(&g_count, 1u);
    __syncthreads();
    if (s_ticket != NBLK - 1) return;

    // Runs after every other block's g_part write is L2-visible.
    // Deterministic: fixed strided fp64 accumulation + fixed shuffle tree.
    double a0 = 0.0, a1 = 0.0, a2 = 0.0, a3 = 0.0;
    for (int r = threadIdx.x; r < NBLK; r += NTHR) {
        a0 += (double)__ldcg(&g_part[r * 4 + 0]);
        a1 += (double)__ldcg(&g_part[r * 4 + 1]);
        a2 += (double)__ldcg(&g_part[r * 4 + 2]);
        a3 += (double)__ldcg(&g_part[r * 4 + 3]);
    }
    #pragma unroll
    for (int o = 16; o > 0; o >>= 1) {
        a0 += __shfl_down_sync(0xffffffffu, a0, o);
        a1 += __shfl_down_sync(0xffffffffu, a1, o);
        a2 += __shfl_down_sync(0xffffffffu, a2, o);
        a3 += __shfl_down_sync(0xffffffffu, a3, o);
    }
    __shared__ double dm[8][4];
    if (lane == 0) {
        dm[wid][0] = a0; dm[wid][1] = a1; dm[wid][2] = a2; dm[wid][3] = a3;
    }
    __syncthreads();
    if (threadIdx.x == 0) {
        double S = 0, TP = 0, SP = 0, ST = 0;
        #pragma unroll
        for (int w = 0; w < 8; w++) {
            S += dm[w][0]; TP += dm[w][1]; SP += dm[w][2]; ST += dm[w][3];
        }
        const double surface = S / (double)NVOX;
        const double fpd = SP - TP;       // sum((1-t)*p)
        const double fnd = ST - TP;       // sum(t*(1-p))
        const double tversky =
            1.0 - (TP + 1.0) / (TP + 0.5 * fpd + 0.5 * fnd + 1.0);
        out[0] = (float)(surface + tversky);
        g_count = 0;                      // reset for next graph replay
    }
}

extern "C" void kernel_launch(void* const* d_in, const int* in_sizes, int n_in,
                              void* d_out, int out_size)
{
    const float* probs  = (const float*)d_in[0];
    const float* target = (const float*)d_in[1];
    float* out = (float*)d_out;

    combined_loss_fused<<<NBLK, NTHR>>>(probs, target, out);
}

// round 7
// speedup vs baseline: 1.2691x; 1.2691x over previous
#include <cuda_runtime.h>

// CombinedLoss: surface(idc=[1]) + tversky(alpha=beta=0.5, smooth=1)
//
// Analytic collapse (exact): the reference EDT runs over 4 axes INCLUDING the
// channel axis of a one-hot(argmax) mask with C=3, so every pos/neg voxel of
// channel 1 has a unit-distance neighbor along the channel axis:
//   dist_maps[:,1] = 1{argmax(probs, axis=1) != 1}
//   surface = mean(probs[:,1] * 1{argmax != 1})       over B*D*H*W voxels
//   tversky = 1 - (tp+1)/(tp + 0.5*(sum_p - tp) + 0.5*(sum_t - tp) + 1)
// argmax first-occurrence: argmax==1 iff p1 > p0 && p1 >= p2.
//
// Shapes: probs/target [B=2, C=3, D=64, H=128, W=128] fp32. Output: scalar.
//
// R3 lesson: __launch_bounds__(256,8) capped regs at 32 < 48 needed for the
// 12 in-flight float4 loads -> ptxas serialized them (MLP_eff ~4, latency
// bound, 19us, DRAM 30%). Fix: occ=4 -> 64 regs/thread, grid 512 (< 592 =
// 148*4, single balanced wave), 2 iterations x 12 front-batched LDG.128.

#define SPATIAL   (64 * 128 * 128)       // 1,048,576 per (b,c)
#define SPATIAL4  (SPATIAL / 4)          // 262,144 float4 groups per (b,c)
#define NVOX      (2 * SPATIAL)          // 2,097,152 voxels
#define NBLK      512
#define NTHR      256
#define NTHREADS  (NBLK * NTHR)          // 131,072 = SPATIAL4 / 2

__device__ float g_part[NBLK * 4];
__device__ unsigned int g_count = 0;     // self-resetting (graph-replay safe)

__global__ __launch_bounds__(NTHR, 4)    // 64 regs/thread: 12 float4 fit
void combined_loss_fused(const float* __restrict__ probs,
                         const float* __restrict__ target,
                         float* __restrict__ out)
{
    const int t = blockIdx.x * NTHR + threadIdx.x;    // 0 .. 131071

    float snum = 0.f, tp = 0.f, sp = 0.f, st = 0.f;

    #pragma unroll
    for (int it = 0; it < 2; ++it) {
        const int s4 = t + it * NTHREADS;             // two balanced passes
        const int e0 = s4 * 4;                        // batch 0
        const int e1 = 3 * SPATIAL + e0;              // batch 1

        // 12 independent 128-bit loads, all live simultaneously (48 regs).
        const float4 A0 = *(const float4*)(probs  + e0);
        const float4 A1 = *(const float4*)(probs  + e0 + SPATIAL);
        const float4 A2 = *(const float4*)(probs  + e0 + 2 * SPATIAL);
        const float4 B0 = *(const float4*)(probs  + e1);
        const float4 B1 = *(const float4*)(probs  + e1 + SPATIAL);
        const float4 B2 = *(const float4*)(probs  + e1 + 2 * SPATIAL);
        const float4 X0 = *(const float4*)(target + e0);
        const float4 X1 = *(const float4*)(target + e0 + SPATIAL);
        const float4 X2 = *(const float4*)(target + e0 + 2 * SPATIAL);
        const float4 Y0 = *(const float4*)(target + e1);
        const float4 Y1 = *(const float4*)(target + e1 + SPATIAL);
        const float4 Y2 = *(const float4*)(target + e1 + 2 * SPATIAL);

#define LANE(P0, P1, P2, T0, T1, T2, k) do {                          \
            const float a = P0.k, q = P1.k, c = P2.k;                 \
            const float x = T0.k, y = T1.k, z = T2.k;                 \
            /* argmax != 1  <=>  !(p1 > p0 && p1 >= p2) */            \
            if (a >= q || c > q) snum += q;                           \
            tp += a * x + q * y + c * z;                              \
            sp += a + q + c;                                          \
            st += x + y + z;                                          \
        } while (0)

        LANE(A0, A1, A2, X0, X1, X2, x);
        LANE(A0, A1, A2, X0, X1, X2, y);
        LANE(A0, A1, A2, X0, X1, X2, z);
        LANE(A0, A1, A2, X0, X1, X2, w);
        LANE(B0, B1, B2, Y0, Y1, Y2, x);
        LANE(B0, B1, B2, Y0, Y1, Y2, y);
        LANE(B0, B1, B2, Y0, Y1, Y2, z);
        LANE(B0, B1, B2, Y0, Y1, Y2, w);
#undef LANE
    }

    // intra-warp tree reduction of the 4 accumulators
    #pragma unroll
    for (int o = 16; o > 0; o >>= 1) {
        snum += __shfl_down_sync(0xffffffffu, snum, o);
        tp   += __shfl_down_sync(0xffffffffu, tp,   o);
        sp   += __shfl_down_sync(0xffffffffu, sp,   o);
        st   += __shfl_down_sync(0xffffffffu, st,   o);
    }

    __shared__ float sm[8][4];
    const int lane = threadIdx.x & 31;
    const int wid  = threadIdx.x >> 5;
    if (lane == 0) {
        sm[wid][0] = snum; sm[wid][1] = tp; sm[wid][2] = sp; sm[wid][3] = st;
    }
    __syncthreads();

    if (threadIdx.x < 32) {
        float v0 = (lane < 8) ? sm[lane][0] : 0.f;
        float v1 = (lane < 8) ? sm[lane][1] : 0.f;
        float v2 = (lane < 8) ? sm[lane][2] : 0.f;
        float v3 = (lane < 8) ? sm[lane][3] : 0.f;
        #pragma unroll
        for (int o = 4; o > 0; o >>= 1) {
            v0 += __shfl_down_sync(0xffffffffu, v0, o);
            v1 += __shfl_down_sync(0xffffffffu, v1, o);
            v2 += __shfl_down_sync(0xffffffffu, v2, o);
            v3 += __shfl_down_sync(0xffffffffu, v3, o);
        }
        if (lane == 0) {
            g_part[blockIdx.x * 4 + 0] = v0;
            g_part[blockIdx.x * 4 + 1] = v1;
            g_part[blockIdx.x * 4 + 2] = v2;
            g_part[blockIdx.x * 4 + 3] = v3;
        }
    }

    // ---- fused last-block finisher (single launch in the graph) ----
    __shared__ unsigned int s_ticket;
    __threadfence();                      // publish g_part before the ticket
    __syncthreads();
    if (threadIdx.x == 0)
        s_ticket = atomicAdd(&g_count, 1u);
    __syncthreads();
    if (s_ticket != NBLK - 1) return;

    // Runs after every other block's g_part write is L2-visible.
    // Deterministic: fixed strided fp64 accumulation + fixed shuffle tree.
    double a0 = 0.0, a1 = 0.0, a2 = 0.0, a3 = 0.0;
    for (int r = threadIdx.x; r < NBLK; r += NTHR) {
        a0 += (double)__ldcg(&g_part[r * 4 + 0]);
        a1 += (double)__ldcg(&g_part[r * 4 + 1]);
        a2 += (double)__ldcg(&g_part[r * 4 + 2]);
        a3 += (double)__ldcg(&g_part[r * 4 + 3]);
    }
    #pragma unroll
    for (int o = 16; o > 0; o >>= 1) {
        a0 += __shfl_down_sync(0xffffffffu, a0, o);
        a1 += __shfl_down_sync(0xffffffffu, a1, o);
        a2 += __shfl_down_sync(0xffffffffu, a2, o);
        a3 += __shfl_down_sync(0xffffffffu, a3, o);
    }
    __shared__ double dm[8][4];
    if (lane == 0) {
        dm[wid][0] = a0; dm[wid][1] = a1; dm[wid][2] = a2; dm[wid][3] = a3;
    }
    __syncthreads();
    if (threadIdx.x == 0) {
        double S = 0, TP = 0, SP = 0, ST = 0;
        #pragma unroll
        for (int w = 0; w < 8; w++) {
            S += dm[w][0]; TP += dm[w][1]; SP += dm[w][2]; ST += dm[w][3];
        }
        const double surface = S / (double)NVOX;
        const double fpd = SP - TP;       // sum((1-t)*p)
        const double fnd = ST - TP;       // sum(t*(1-p))
        const double tversky =
            1.0 - (TP + 1.0) / (TP + 0.5 * fpd + 0.5 * fnd + 1.0);
        out[0] = (float)(surface + tversky);
        g_count = 0;                      // reset for next graph replay
    }
}

extern "C" void kernel_launch(void* const* d_in, const int* in_sizes, int n_in,
                              void* d_out, int out_size)
{
    const float* probs  = (const float*)d_in[0];
    const float* target = (const float*)d_in[1];
    float* out = (float*)d_out;

    combined_loss_fused<<<NBLK, NTHR>>>(probs, target, out);
}

// round 8
// speedup vs baseline: 1.3050x; 1.0283x over previous
#include <cuda_runtime.h>
#include <cstdint>

// CombinedLoss: surface(idc=[1]) + tversky(alpha=beta=0.5, smooth=1)
//
// Analytic collapse (exact): the reference EDT runs over 4 axes INCLUDING the
// channel axis of a one-hot(argmax) mask with C=3, so channel 1 distances are
// identically 1:
//   dist_maps[:,1] = 1{argmax(probs, axis=1) != 1}
//   surface = mean(probs[:,1] * 1{argmax != 1})       over B*D*H*W voxels
//   tversky = 1 - (tp+1)/(tp + 0.5*(sum_p - tp) + 0.5*(sum_t - tp) + 1)
// argmax first-occurrence: argmax==1 iff p1 > p0 && p1 >= p2.
//
// R7 lesson: LDG-path streaming saturates the per-SM L1tex in-flight queue
// (~248 wavefronts) at ~2.8-3.3 TB/s regardless of register MLP/occupancy.
// This version streams via cp.async.bulk (TMA engine) into double-buffered
// SMEM stages — in-flight bytes bounded by smem, not the L1tex queue.
//
// Geometry: persistent 296 CTAs (=148*2) x 256 thr, 2 CTAs/SM (96KB smem).
// 1024 stages of 256 float4-groups; stage = 12 streams x 4KB = 48KB.

#define SPATIAL       (64 * 128 * 128)    // 1,048,576 floats per (b,c)
#define SPATIAL4      (SPATIAL / 4)       // 262,144 float4 groups per batch
#define NVOX          (2 * SPATIAL)       // 2,097,152 voxels
#define NBLK          296
#define NTHR          256
#define NSTAGES_TOT   1024                // SPATIAL4 / 256
#define STAGE_GROUPS  256                 // float4 groups per stage
#define STREAM_BYTES  4096                // 256 groups * 16B
#define STAGE_BYTES   (12 * STREAM_BYTES) // 49152
#define SMEM_BYTES    (2 * STAGE_BYTES)   // 98304 (double buffer)

__device__ float g_part[NBLK * 4];
__device__ unsigned int g_count = 0;      // self-resetting (graph-replay safe)

__device__ __forceinline__ uint32_t smem_u32(const void* p) {
    uint32_t a;
    asm("{ .reg .u64 t; cvta.to.shared.u64 t, %1; cvt.u32.u64 %0, t; }"
        : "=r"(a) : "l"(p));
    return a;
}

__device__ __forceinline__ void mbar_init(uint32_t mbar, uint32_t count) {
    asm volatile("mbarrier.init.shared.b64 [%0], %1;" :: "r"(mbar), "r"(count)
                 : "memory");
}

__device__ __forceinline__ void mbar_expect_tx(uint32_t mbar, uint32_t bytes) {
    asm volatile("mbarrier.arrive.expect_tx.shared.b64 _, [%0], %1;"
                 :: "r"(mbar), "r"(bytes) : "memory");
}

__device__ __forceinline__ void mbar_wait(uint32_t mbar, uint32_t parity) {
    asm volatile(
        "{\n\t"
        ".reg .pred P;\n\t"
        "WL_%=:\n\t"
        "mbarrier.try_wait.parity.acquire.cta.shared::cta.b64 P, [%0], %1, 0x989680;\n\t"
        "@P bra WD_%=;\n\t"
        "bra WL_%=;\n\t"
        "WD_%=:\n\t"
        "}"
        :: "r"(mbar), "r"(parity) : "memory");
}

__device__ __forceinline__ void bulk_copy(uint32_t smem_dst,
                                          const void* gmem_src,
                                          uint32_t bytes, uint32_t mbar) {
    asm volatile(
        "cp.async.bulk.shared::cluster.global.mbarrier::complete_tx::bytes "
        "[%0], [%1], %2, [%3];"
        :: "r"(smem_dst), "l"(gmem_src), "r"(bytes), "r"(mbar) : "memory");
}

__global__ __launch_bounds__(NTHR)
void combined_loss_bulk(const float* __restrict__ probs,
                        const float* __restrict__ target,
                        float* __restrict__ out)
{
    extern __shared__ __align__(16) char smem[];
    __shared__ __align__(8) unsigned long long barrier_storage[2];

    const int tid  = threadIdx.x;
    const int bid  = blockIdx.x;
    const uint32_t smem_base = smem_u32(smem);
    const uint32_t bar0 = smem_u32(&barrier_storage[0]);
    const uint32_t bar1 = smem_u32(&barrier_storage[1]);

    // number of stages owned by this CTA: st_i = bid + i*NBLK < NSTAGES_TOT
    const int nst = (NSTAGES_TOT - bid + NBLK - 1) / NBLK;

    if (tid == 0) {
        mbar_init(bar0, 1);
        mbar_init(bar1, 1);
    }
    __syncthreads();

    // 12 stream base pointers (floats). Streams 0-5: probs (b0c0..b1c2);
    // streams 6-11: target same order.
    const float* sbase[12];
    #pragma unroll
    for (int c = 0; c < 6; c++) {
        sbase[c]     = probs  + c * SPATIAL;
        sbase[6 + c] = target + c * SPATIAL;
    }

    // Prologue: issue first two stages.
    if (tid == 0) {
        #pragma unroll
        for (int j = 0; j < 2; j++) {
            if (j < nst) {
                const int st = bid + j * NBLK;
                const uint32_t bar = j ? bar1 : bar0;
                const uint32_t dst = smem_base + j * STAGE_BYTES;
                mbar_expect_tx(bar, STAGE_BYTES);
                const int foff = st * (STAGE_GROUPS * 4);   // float offset
                #pragma unroll
                for (int s = 0; s < 12; s++)
                    bulk_copy(dst + s * STREAM_BYTES, sbase[s] + foff,
                              STREAM_BYTES, bar);
            }
        }
    }

    float snum = 0.f, tp = 0.f, sp = 0.f, st_acc = 0.f;

    for (int i = 0; i < nst; i++) {
        const int buf = i & 1;
        mbar_wait(buf ? bar1 : bar0, (i >> 1) & 1);

        // Compute: thread t owns group t of this stage (float4 per stream).
        const char* b = smem + buf * STAGE_BYTES;
        const int o = tid * 16;
        const float4 A0 = *(const float4*)(b + 0  * STREAM_BYTES + o);
        const float4 A1 = *(const float4*)(b + 1  * STREAM_BYTES + o);
        const float4 A2 = *(const float4*)(b + 2  * STREAM_BYTES + o);
        const float4 B0 = *(const float4*)(b + 3  * STREAM_BYTES + o);
        const float4 B1 = *(const float4*)(b + 4  * STREAM_BYTES + o);
        const float4 B2 = *(const float4*)(b + 5  * STREAM_BYTES + o);
        const float4 X0 = *(const float4*)(b + 6  * STREAM_BYTES + o);
        const float4 X1 = *(const float4*)(b + 7  * STREAM_BYTES + o);
        const float4 X2 = *(const float4*)(b + 8  * STREAM_BYTES + o);
        const float4 Y0 = *(const float4*)(b + 9  * STREAM_BYTES + o);
        const float4 Y1 = *(const float4*)(b + 10 * STREAM_BYTES + o);
        const float4 Y2 = *(const float4*)(b + 11 * STREAM_BYTES + o);

#define LANE(P0, P1, P2, T0, T1, T2, k) do {                          \
            const float pa = P0.k, pq = P1.k, pc = P2.k;              \
            const float tx = T0.k, ty = T1.k, tz = T2.k;              \
            /* argmax != 1  <=>  !(p1 > p0 && p1 >= p2) */            \
            if (pa >= pq || pc > pq) snum += pq;                      \
            tp     += pa * tx + pq * ty + pc * tz;                    \
            sp     += pa + pq + pc;                                   \
            st_acc += tx + ty + tz;                                   \
        } while (0)

        LANE(A0, A1, A2, X0, X1, X2, x);
        LANE(A0, A1, A2, X0, X1, X2, y);
        LANE(A0, A1, A2, X0, X1, X2, z);
        LANE(A0, A1, A2, X0, X1, X2, w);
        LANE(B0, B1, B2, Y0, Y1, Y2, x);
        LANE(B0, B1, B2, Y0, Y1, Y2, y);
        LANE(B0, B1, B2, Y0, Y1, Y2, z);
        LANE(B0, B1, B2, Y0, Y1, Y2, w);
#undef LANE

        __syncthreads();                 // all threads done reading buf

        if (tid == 0 && i + 2 < nst) {   // re-arm this buffer for stage i+2
            const int stg = bid + (i + 2) * NBLK;
            const uint32_t bar = buf ? bar1 : bar0;
            const uint32_t dst = smem_base + buf * STAGE_BYTES;
            mbar_expect_tx(bar, STAGE_BYTES);
            const int foff = stg * (STAGE_GROUPS * 4);
            #pragma unroll
            for (int s = 0; s < 12; s++)
                bulk_copy(dst + s * STREAM_BYTES, sbase[s] + foff,
                          STREAM_BYTES, bar);
        }
    }

    // ---- block reduction of the 4 accumulators ----
    #pragma unroll
    for (int o = 16; o > 0; o >>= 1) {
        snum   += __shfl_down_sync(0xffffffffu, snum,   o);
        tp     += __shfl_down_sync(0xffffffffu, tp,     o);
        sp     += __shfl_down_sync(0xffffffffu, sp,     o);
        st_acc += __shfl_down_sync(0xffffffffu, st_acc, o);
    }

    __shared__ float sm[8][4];
    const int lane = tid & 31;
    const int wid  = tid >> 5;
    if (lane == 0) {
        sm[wid][0] = snum; sm[wid][1] = tp; sm[wid][2] = sp; sm[wid][3] = st_acc;
    }
    __syncthreads();

    if (tid < 32) {
        float v0 = (lane < 8) ? sm[lane][0] : 0.f;
        float v1 = (lane < 8) ? sm[lane][1] : 0.f;
        float v2 = (lane < 8) ? sm[lane][2] : 0.f;
        float v3 = (lane < 8) ? sm[lane][3] : 0.f;
        #pragma unroll
        for (int o = 4; o > 0; o >>= 1) {
            v0 += __shfl_down_sync(0xffffffffu, v0, o);
            v1 += __shfl_down_sync(0xffffffffu, v1, o);
            v2 += __shfl_down_sync(0xffffffffu, v2, o);
            v3 += __shfl_down_sync(0xffffffffu, v3, o);
        }
        if (lane == 0) {
            g_part[bid * 4 + 0] = v0;
            g_part[bid * 4 + 1] = v1;
            g_part[bid * 4 + 2] = v2;
            g_part[bid * 4 + 3] = v3;
        }
    }

    // ---- fused last-block finisher ----
    __shared__ unsigned int s_ticket;
    __threadfence();
    __syncthreads();
    if (tid == 0)
        s_ticket = atomicAdd(&g_count, 1u);
    __syncthreads();
    if (s_ticket != NBLK - 1) return;

    double a0 = 0.0, a1 = 0.0, a2 = 0.0, a3 = 0.0;
    for (int r = tid; r < NBLK; r += NTHR) {
        a0 += (double)__ldcg(&g_part[r * 4 + 0]);
        a1 += (double)__ldcg(&g_part[r * 4 + 1]);
        a2 += (double)__ldcg(&g_part[r * 4 + 2]);
        a3 += (double)__ldcg(&g_part[r * 4 + 3]);
    }
    #pragma unroll
    for (int o = 16; o > 0; o >>= 1) {
        a0 += __shfl_down_sync(0xffffffffu, a0, o);
        a1 += __shfl_down_sync(0xffffffffu, a1, o);
        a2 += __shfl_down_sync(0xffffffffu, a2, o);
        a3 += __shfl_down_sync(0xffffffffu, a3, o);
    }
    __shared__ double dm[8][4];
    if (lane == 0) {
        dm[wid][0] = a0; dm[wid][1] = a1; dm[wid][2] = a2; dm[wid][3] = a3;
    }
    __syncthreads();
    if (tid == 0) {
        double S = 0, TP = 0, SP = 0, ST = 0;
        #pragma unroll
        for (int w = 0; w < 8; w++) {
            S += dm[w][0]; TP += dm[w][1]; SP += dm[w][2]; ST += dm[w][3];
        }
        const double surface = S / (double)NVOX;
        const double fpd = SP - TP;       // sum((1-t)*p)
        const double fnd = ST - TP;       // sum(t*(1-p))
        const double tversky =
            1.0 - (TP + 1.0) / (TP + 0.5 * fpd + 0.5 * fnd + 1.0);
        out[0] = (float)(surface + tversky);
        g_count = 0;                      // reset for next graph replay
    }
}

extern "C" void kernel_launch(void* const* d_in, const int* in_sizes, int n_in,
                              void* d_out, int out_size)
{
    const float* probs  = (const float*)d_in[0];
    const float* target = (const float*)d_in[1];
    float* out = (float*)d_out;

    cudaFuncSetAttribute(combined_loss_bulk,
                         cudaFuncAttributeMaxDynamicSharedMemorySize,
                         SMEM_BYTES);
    combined_loss_bulk<<<NBLK, NTHR, SMEM_BYTES>>>(probs, target, out);
}